// round 6
// baseline (speedup 1.0000x reference)
#include <cuda_runtime.h>
#include <math.h>

#define NMAX 10000
#define EMAX 320000

// ---------------- scratch (device globals; no allocation allowed) -------------
__device__ int      g_is64;
__device__ float    g_deg[NMAX];
__device__ float    g_dis[NMAX];
__device__ int      g_cnt[NMAX];
__device__ int      g_rowptr[NMAX + 1];
__device__ int      g_srcd[EMAX];
__device__ int      g_dstd[EMAX];
__device__ int2     g_colw[EMAX];            // packed (src col, bitcast norm)
__device__ unsigned g_arrive;                // zero-init; invariant: 0 between barriers
__device__ volatile unsigned g_gen;          // monotonically increasing generation
__device__ __align__(256) float g_h[NMAX * 64];
__device__ __align__(256) float g_acc[NMAX * 64];
__device__ __align__(256) float g_B0[NMAX * 64];
__device__ __align__(256) float g_B1[NMAX * 64];
__device__ __align__(256) float g_B2[NMAX * 64];

constexpr int TPB = 1024;
constexpr int NPB = 32;   // nodes per block-pass (one per warp)

// ---------------- software grid barrier (G blocks, all co-resident) -----------
__device__ __forceinline__ void gbar(int G) {
    __threadfence();          // make this thread's prior writes L2-visible
    __syncthreads();
    if (threadIdx.x == 0) {
        unsigned gen = g_gen;
        if (atomicAdd(&g_arrive, 1u) == (unsigned)G - 1u) {
            g_arrive = 0u;
            __threadfence();
            g_gen = gen + 1u;   // release
        } else {
            while (g_gen == gen) { __nanosleep(64); }
            __threadfence();
        }
    }
    __syncthreads();
}

// ---------------- per-layer device routine ------------------------------------
// All K Chebyshev steps; grid barrier after each step.
// Per step k: T_k per node into Ts (smem) + dst buffer, then block GEMM
// acc[node,:] (+)= T_k[node,:] @ W_k (+ bias at k=0).
template <int IN, int OUT>
__device__ __forceinline__ void layer_run(const float* __restrict__ h0,
                                          float* __restrict__ acc,
                                          const float* __restrict__ W,
                                          const float* __restrict__ bias,
                                          int K, int n, int G,
                                          float* Ts, float* Ws) {
    constexpr int ST = (IN % 16 == 0) ? IN : IN + 1;   // smem row stride
    int tid  = threadIdx.x;
    int wrp  = tid >> 5;
    int lane = tid & 31;

    const float* src = h0;      // T_{k-1}
    const float* prv = nullptr; // T_{k-2}
    float* rot0 = g_B1; float* rot1 = g_B2; float* rot2 = g_B0;

    int tiles = (n + G * NPB - 1) / (G * NPB);

    for (int k = 0; k < K; k++) {
        for (int i = tid; i < IN * OUT; i += TPB) Ws[i] = W[k * IN * OUT + i];

        float* dst = nullptr;
        if (k >= 1) {
            int r = (k - 1) % 3;
            dst = (r == 0) ? rot0 : (r == 1) ? rot1 : rot2;
        }

        for (int p = 0; p < tiles; p++) {
            int base = (p * G + blockIdx.x) * NPB;
            int nd = base + wrp;
            float* tsw = Ts + wrp * ST;
            if (nd < n) {
                if (k == 0) {
                    for (int f = lane; f < IN; f += 32) tsw[f] = h0[nd * IN + f];
                } else if (IN == 4) {
                    // lane-per-edge float4 gather
                    int beg = g_rowptr[nd], end = g_rowptr[nd + 1];
                    float4 s = make_float4(0.f, 0.f, 0.f, 0.f);
                    for (int e = beg + lane; e < end; e += 32) {
                        int2 cw = __ldg(&g_colw[e]);
                        float nv = __int_as_float(cw.y);
                        float4 v = __ldg((const float4*)(src + cw.x * 4));
                        s.x += nv * v.x; s.y += nv * v.y;
                        s.z += nv * v.z; s.w += nv * v.w;
                    }
#pragma unroll
                    for (int off = 16; off >= 1; off >>= 1) {
                        s.x += __shfl_xor_sync(0xffffffffu, s.x, off);
                        s.y += __shfl_xor_sync(0xffffffffu, s.y, off);
                        s.z += __shfl_xor_sync(0xffffffffu, s.z, off);
                        s.w += __shfl_xor_sync(0xffffffffu, s.w, off);
                    }
                    if (lane == 0) {
                        float4 t = s;
                        if (k >= 2) {
                            float4 q = __ldg((const float4*)(prv + nd * 4));
                            t.x = 2.f * s.x - q.x; t.y = 2.f * s.y - q.y;
                            t.z = 2.f * s.z - q.z; t.w = 2.f * s.w - q.w;
                        }
                        *((float4*)(dst + nd * 4)) = t;
                        tsw[0] = t.x; tsw[1] = t.y; tsw[2] = t.z; tsw[3] = t.w;
                    }
                } else if (IN % 16 == 0) {
                    // half-warp per edge, float4 per lane, unrolled x4 for MLP
                    int beg = g_rowptr[nd], end = g_rowptr[nd + 1];
                    int half = lane >> 4;
                    int fl   = lane & 15;
                    float4 a0 = make_float4(0.f, 0.f, 0.f, 0.f);
                    float4 a1 = make_float4(0.f, 0.f, 0.f, 0.f);
                    float4 a2 = make_float4(0.f, 0.f, 0.f, 0.f);
                    float4 a3 = make_float4(0.f, 0.f, 0.f, 0.f);
                    int e = beg + half;
                    for (; e + 6 < end; e += 8) {
                        int2 c0 = __ldg(&g_colw[e]);
                        int2 c1 = __ldg(&g_colw[e + 2]);
                        int2 c2 = __ldg(&g_colw[e + 4]);
                        int2 c3 = __ldg(&g_colw[e + 6]);
                        float4 v0 = __ldg(((const float4*)(src + c0.x * IN)) + fl);
                        float4 v1 = __ldg(((const float4*)(src + c1.x * IN)) + fl);
                        float4 v2 = __ldg(((const float4*)(src + c2.x * IN)) + fl);
                        float4 v3 = __ldg(((const float4*)(src + c3.x * IN)) + fl);
                        float n0 = __int_as_float(c0.y);
                        float n1 = __int_as_float(c1.y);
                        float n2 = __int_as_float(c2.y);
                        float n3 = __int_as_float(c3.y);
                        a0.x += n0 * v0.x; a0.y += n0 * v0.y;
                        a0.z += n0 * v0.z; a0.w += n0 * v0.w;
                        a1.x += n1 * v1.x; a1.y += n1 * v1.y;
                        a1.z += n1 * v1.z; a1.w += n1 * v1.w;
                        a2.x += n2 * v2.x; a2.y += n2 * v2.y;
                        a2.z += n2 * v2.z; a2.w += n2 * v2.w;
                        a3.x += n3 * v3.x; a3.y += n3 * v3.y;
                        a3.z += n3 * v3.z; a3.w += n3 * v3.w;
                    }
                    for (; e < end; e += 2) {
                        int2 cw = __ldg(&g_colw[e]);
                        float nv = __int_as_float(cw.y);
                        float4 v = __ldg(((const float4*)(src + cw.x * IN)) + fl);
                        a0.x += nv * v.x; a0.y += nv * v.y;
                        a0.z += nv * v.z; a0.w += nv * v.w;
                    }
                    float4 s = make_float4(a0.x + a1.x + a2.x + a3.x,
                                           a0.y + a1.y + a2.y + a3.y,
                                           a0.z + a1.z + a2.z + a3.z,
                                           a0.w + a1.w + a2.w + a3.w);
                    s.x += __shfl_xor_sync(0xffffffffu, s.x, 16);
                    s.y += __shfl_xor_sync(0xffffffffu, s.y, 16);
                    s.z += __shfl_xor_sync(0xffffffffu, s.z, 16);
                    s.w += __shfl_xor_sync(0xffffffffu, s.w, 16);
                    if (lane < 16) {
                        float4 t = s;
                        if (k >= 2) {
                            float4 q = __ldg(((const float4*)(prv + nd * IN)) + fl);
                            t.x = 2.f * s.x - q.x; t.y = 2.f * s.y - q.y;
                            t.z = 2.f * s.z - q.z; t.w = 2.f * s.w - q.w;
                        }
                        ((float4*)(dst + nd * IN))[fl] = t;
                        ((float4*)tsw)[fl] = t;
                    }
                } else {
                    // odd width (IN=60): lane-per-feature scalar path
                    int beg = g_rowptr[nd], end = g_rowptr[nd + 1];
                    int f0 = lane, f1 = lane + 32;
                    float s0 = 0.f, s1 = 0.f;
                    for (int e = beg; e < end; e++) {
                        int2 cw = __ldg(&g_colw[e]);
                        float nv = __int_as_float(cw.y);
                        const float* rp = src + cw.x * IN;
                        s0 += nv * __ldg(&rp[f0]);
                        if (f1 < IN) s1 += nv * __ldg(&rp[f1]);
                    }
                    {
                        float t0 = (k >= 2) ? 2.f * s0 - prv[nd * IN + f0] : s0;
                        dst[nd * IN + f0] = t0;
                        tsw[f0] = t0;
                    }
                    if (f1 < IN) {
                        float t1 = (k >= 2) ? 2.f * s1 - prv[nd * IN + f1] : s1;
                        dst[nd * IN + f1] = t1;
                        tsw[f1] = t1;
                    }
                }
            }
            __syncthreads();

            // block GEMM: acc[node, j] (+)= sum_i Ts[node][i] * Ws[i][j]
            constexpr int JS     = (OUT > 32) ? 64 : 32;
            constexpr int GROUPS = TPB / JS;
            constexpr int NPG    = NPB / GROUPS;
            int j = tid % JS;
            int g = tid / JS;
            if (j < OUT) {
                float a[NPG];
#pragma unroll
                for (int q = 0; q < NPG; q++) a[q] = 0.f;
#pragma unroll 4
                for (int i = 0; i < IN; i++) {
                    float wv = Ws[i * OUT + j];
#pragma unroll
                    for (int q = 0; q < NPG; q++)
                        a[q] += wv * Ts[(g * NPG + q) * ST + i];
                }
#pragma unroll
                for (int q = 0; q < NPG; q++) {
                    int node = base + g * NPG + q;
                    if (node < n) {
                        if (k == 0)
                            acc[node * OUT + j] = a[q] + __ldg(&bias[j]);
                        else
                            acc[node * OUT + j] += a[q];
                    }
                }
            }
            __syncthreads();
        }

        if (k >= 1) { prv = src; src = dst; }
        gbar(G);   // T_k fully written & acc updated before step k+1 gathers
    }
}

// ---------------- the single fused kernel -------------------------------------
__global__ __launch_bounds__(TPB, 1)
void fused_all(const float* __restrict__ x, const void* __restrict__ ei,
               const float* __restrict__ ew,
               const float* __restrict__ W1, const float* __restrict__ b1,
               const float* __restrict__ W2, const float* __restrict__ b2,
               const float* __restrict__ W3, const float* __restrict__ b3,
               const float* __restrict__ W4,
               float* __restrict__ out, int n, int E, int G) {
    __shared__ __align__(16) float Ts[NPB * 65];
    __shared__ float Ws[64 * 60];

    int tid = threadIdx.x;
    int bid = blockIdx.x;
    int gsz = G * TPB;
    int gid = bid * TPB + tid;

    // phase 0: zero counters + detect int64-vs-int32 edge_index layout
    for (int i = gid; i < n; i += gsz) { g_deg[i] = 0.f; g_cnt[i] = 0; }
    if (bid == 0) {
        __shared__ int bad;
        if (tid == 0) bad = 0;
        __syncthreads();
        int nsamp = E / 2;
        if (nsamp > 4096) nsamp = 4096;
        const int* p32 = (const int*)ei;
        for (int i = tid; i < nsamp; i += TPB)
            if (p32[2 * i + 1] != 0) bad = 1;
        __syncthreads();
        if (tid == 0) g_is64 = (bad == 0) ? 1 : 0;
    }
    gbar(G);

    // phase 1: decode edges (clamped) + degree & in-count
    {
        int is64 = g_is64;
        for (int e = gid; e < E; e += gsz) {
            int s, d;
            if (is64) {
                const long long* p = (const long long*)ei;
                s = (int)p[e];
                d = (int)p[(long long)E + e];
            } else {
                const int* p = (const int*)ei;
                s = p[e];
                d = p[E + e];
            }
            s = (s < 0) ? 0 : ((s >= n) ? n - 1 : s);
            d = (d < 0) ? 0 : ((d >= n) ? n - 1 : d);
            g_srcd[e] = s;
            g_dstd[e] = d;
            atomicAdd(&g_deg[s], ew[e]);
            atomicAdd(&g_cnt[d], 1);
        }
    }
    gbar(G);

    // phase 2: dis + exclusive scan (block 0 only)
    if (bid == 0) {
        for (int i = tid; i < n; i += TPB) {
            float d = g_deg[i];
            g_dis[i] = (d > 0.f) ? (1.f / sqrtf(d)) : 0.f;
        }
        __syncthreads();
        __shared__ int ssum[TPB];
        int chunk = (n + TPB - 1) / TPB;
        int beg = tid * chunk; if (beg > n) beg = n;
        int end = beg + chunk; if (end > n) end = n;
        int s = 0;
        for (int i = beg; i < end; i++) s += g_cnt[i];
        ssum[tid] = s;
        __syncthreads();
        for (int off = 1; off < TPB; off <<= 1) {
            int v = (tid >= off) ? ssum[tid - off] : 0;
            __syncthreads();
            ssum[tid] += v;
            __syncthreads();
        }
        int run = (tid == 0) ? 0 : ssum[tid - 1];
        for (int i = beg; i < end; i++) {
            int c = g_cnt[i];
            g_rowptr[i] = run;
            g_cnt[i] = run;   // cursor for scatter
            run += c;
        }
        if (tid == TPB - 1) g_rowptr[n] = ssum[TPB - 1];
    }
    gbar(G);

    // phase 3: scatter packed (col, norm) into CSR order
    for (int e = gid; e < E; e += gsz) {
        int s = g_srcd[e], d = g_dstd[e];
        float nv = -g_dis[s] * ew[e] * g_dis[d];
        int p = atomicAdd(&g_cnt[d], 1);
        g_colw[p] = make_int2(s, __float_as_int(nv));
    }
    gbar(G);

    // layer 1: ChebConv(4 -> 64, K=120) + SiLU
    layer_run<4, 64>(x, g_acc, W1, b1, 120, n, G, Ts, Ws);
    for (int i = gid; i < n * 64; i += gsz) {
        float v = g_acc[i];
        g_h[i] = v / (1.f + expf(-v));
    }
    gbar(G);

    // layer 2: ChebConv(64 -> 60, K=120) + SiLU  (input g_h no longer needed
    // after layer_run's final barrier, so reuse it for the silu output)
    layer_run<64, 60>(g_h, g_acc, W2, b2, 120, n, G, Ts, Ws);
    for (int i = gid; i < n * 60; i += gsz) {
        float v = g_acc[i];
        g_h[i] = v / (1.f + expf(-v));
    }
    gbar(G);

    // layer 3: ChebConv(60 -> 30, K=20) + SiLU
    layer_run<60, 30>(g_h, g_acc, W3, b3, 20, n, G, Ts, Ws);
    for (int i = gid; i < n * 30; i += gsz) {
        float v = g_acc[i];
        g_h[i] = v / (1.f + expf(-v));
    }
    gbar(G);

    // layer 4: ChebConv(30 -> 1, K=1) + sigmoid
    for (int i = gid; i < n; i += gsz) {
        float s = 0.f;
        const float* hp = g_h + i * 30;
#pragma unroll
        for (int k = 0; k < 30; k++) s += hp[k] * __ldg(&W4[k]);
        out[i] = 1.f / (1.f + expf(-s));
    }
}

// ---------------- host orchestration ------------------------------------------
extern "C" void kernel_launch(void* const* d_in, const int* in_sizes, int n_in,
                              void* d_out, int out_size) {
    const float* x  = (const float*)d_in[0];
    const void*  ei = d_in[1];
    const float* ew = (const float*)d_in[2];
    const float* W1 = (const float*)d_in[3];
    const float* b1 = (const float*)d_in[4];
    const float* W2 = (const float*)d_in[5];
    const float* b2 = (const float*)d_in[6];
    const float* W3 = (const float*)d_in[7];
    const float* b3 = (const float*)d_in[8];
    const float* W4 = (const float*)d_in[9];
    float* out = (float*)d_out;

    int n = in_sizes[0] / 4;   // 10000
    int E = in_sizes[2];       // 320000

    static int G = 0;
    if (G == 0) {
        int dev = 0;
        cudaGetDevice(&dev);
        int sms = 0;
        cudaDeviceGetAttribute(&sms, cudaDevAttrMultiProcessorCount, dev);
        int bps = 0;
        cudaOccupancyMaxActiveBlocksPerMultiprocessor(&bps, fused_all, TPB, 0);
        if (sms <= 0) sms = 148;
        if (bps <= 0) bps = 1;
        if (bps > 2) bps = 2;
        G = sms * bps;
    }

    fused_all<<<G, TPB>>>(x, ei, ew, W1, b1, W2, b2, W3, b3, W4, out, n, E, G);
}

// round 7
// speedup vs baseline: 1.3162x; 1.3162x over previous
#include <cuda_runtime.h>
#include <math.h>

#define NMAX 10000
#define EMAX 320000

// ---------------- scratch (device globals; no allocation allowed) -------------
__device__ int      g_is64;
__device__ float    g_deg[NMAX];
__device__ float    g_dis[NMAX];
__device__ int      g_cnt[NMAX];
__device__ int      g_rowptr[NMAX + 1];
__device__ int      g_srcd[EMAX];
__device__ int      g_dstd[EMAX];
__device__ int2     g_colw[EMAX];            // packed (src col, bitcast norm)
__device__ unsigned g_arrive;                // zero-init; 0 between barriers
__device__ volatile unsigned g_gen;          // generation counter
__device__ __align__(256) float g_h[NMAX * 64];
__device__ __align__(256) float g_acc[NMAX * 64];
__device__ __align__(256) float g_B0[NMAX * 64];
__device__ __align__(256) float g_B1[NMAX * 64];
__device__ __align__(256) float g_B2[NMAX * 64];

constexpr int TPB = 256;
constexpr int NPB = 8;    // nodes per block-pass (one per warp)
constexpr int BPS = 6;    // resident blocks per SM

// ---------------- software grid barrier (G blocks, all co-resident) -----------
__device__ __forceinline__ void gbar(int G) {
    __threadfence();
    __syncthreads();
    if (threadIdx.x == 0) {
        unsigned gen = g_gen;
        if (atomicAdd(&g_arrive, 1u) == (unsigned)G - 1u) {
            g_arrive = 0u;
            __threadfence();
            g_gen = gen + 1u;   // release
        } else {
            while (g_gen == gen) { __nanosleep(64); }
            __threadfence();
        }
    }
    __syncthreads();
}

// ---------------- per-layer device routine ------------------------------------
// All K Chebyshev steps; grid barrier after each step.
template <int IN, int OUT>
__device__ __forceinline__ void layer_run(const float* __restrict__ h0,
                                          float* __restrict__ acc,
                                          const float* __restrict__ W,
                                          const float* __restrict__ bias,
                                          int K, int n, int G,
                                          float* Ts, float* Ws) {
    constexpr int ST = (IN % 16 == 0) ? IN : IN + 1;   // smem row stride
    int tid  = threadIdx.x;
    int wrp  = tid >> 5;
    int lane = tid & 31;

    const float* src = h0;      // T_{k-1}
    const float* prv = nullptr; // T_{k-2}
    float* rot0 = g_B1; float* rot1 = g_B2; float* rot2 = g_B0;

    int tiles = (n + G * NPB - 1) / (G * NPB);

    for (int k = 0; k < K; k++) {
        for (int i = tid; i < IN * OUT; i += TPB) Ws[i] = W[k * IN * OUT + i];

        float* dst = nullptr;
        if (k >= 1) {
            int r = (k - 1) % 3;
            dst = (r == 0) ? rot0 : (r == 1) ? rot1 : rot2;
        }

        for (int p = 0; p < tiles; p++) {
            int base = (p * G + blockIdx.x) * NPB;
            int nd = base + wrp;
            float* tsw = Ts + wrp * ST;
            if (nd < n) {
                if (k == 0) {
                    for (int f = lane; f < IN; f += 32) tsw[f] = h0[nd * IN + f];
                } else if (IN == 4) {
                    // lane-per-edge float4 gather (meta load is coalesced)
                    int beg = g_rowptr[nd], end = g_rowptr[nd + 1];
                    float4 s = make_float4(0.f, 0.f, 0.f, 0.f);
                    for (int e = beg + lane; e < end; e += 32) {
                        int2 cw = __ldg(&g_colw[e]);
                        float nv = __int_as_float(cw.y);
                        float4 v = __ldg((const float4*)(src + cw.x * 4));
                        s.x += nv * v.x; s.y += nv * v.y;
                        s.z += nv * v.z; s.w += nv * v.w;
                    }
#pragma unroll
                    for (int off = 16; off >= 1; off >>= 1) {
                        s.x += __shfl_xor_sync(0xffffffffu, s.x, off);
                        s.y += __shfl_xor_sync(0xffffffffu, s.y, off);
                        s.z += __shfl_xor_sync(0xffffffffu, s.z, off);
                        s.w += __shfl_xor_sync(0xffffffffu, s.w, off);
                    }
                    if (lane == 0) {
                        float4 t = s;
                        if (k >= 2) {
                            float4 q = __ldg((const float4*)(prv + nd * 4));
                            t.x = 2.f * s.x - q.x; t.y = 2.f * s.y - q.y;
                            t.z = 2.f * s.z - q.z; t.w = 2.f * s.w - q.w;
                        }
                        *((float4*)(dst + nd * 4)) = t;
                        tsw[0] = t.x; tsw[1] = t.y; tsw[2] = t.z; tsw[3] = t.w;
                    }
                } else if (IN % 16 == 0) {
                    // Chunked gather: one coalesced meta load for 32 edges,
                    // then broadcast via shuffle; row loads are independent.
                    int beg = g_rowptr[nd], end = g_rowptr[nd + 1];
                    int half = lane >> 4;
                    int fl   = lane & 15;
                    float4 a0 = make_float4(0.f, 0.f, 0.f, 0.f);
                    float4 a1 = make_float4(0.f, 0.f, 0.f, 0.f);
                    for (int cb = beg; cb < end; cb += 32) {
                        int ce = end - cb;           // edges in this chunk
                        if (ce > 32) ce = 32;
                        int2 meta = make_int2(0, 0);
                        if (lane < ce) meta = __ldg(&g_colw[cb + lane]);
                        int jj = 0;
                        // 4 edges per iteration (2 per half-warp), uniform trips
                        for (; jj + 3 < ce; jj += 4) {
                            int e0 = jj + half;
                            int e1 = jj + 2 + half;
                            int c0 = __shfl_sync(0xffffffffu, meta.x, e0);
                            int w0 = __shfl_sync(0xffffffffu, meta.y, e0);
                            int c1 = __shfl_sync(0xffffffffu, meta.x, e1);
                            int w1 = __shfl_sync(0xffffffffu, meta.y, e1);
                            float4 v0 = __ldg(((const float4*)(src + c0 * IN)) + fl);
                            float4 v1 = __ldg(((const float4*)(src + c1 * IN)) + fl);
                            float n0 = __int_as_float(w0);
                            float n1 = __int_as_float(w1);
                            a0.x += n0 * v0.x; a0.y += n0 * v0.y;
                            a0.z += n0 * v0.z; a0.w += n0 * v0.w;
                            a1.x += n1 * v1.x; a1.y += n1 * v1.y;
                            a1.z += n1 * v1.z; a1.w += n1 * v1.w;
                        }
                        // remainder (uniform trips; clamp index, zero weight)
                        for (; jj < ce; jj += 2) {
                            int e0 = jj + half;
                            int idx = (e0 < ce) ? e0 : (ce - 1);
                            int c0 = __shfl_sync(0xffffffffu, meta.x, idx);
                            int w0 = __shfl_sync(0xffffffffu, meta.y, idx);
                            float n0 = (e0 < ce) ? __int_as_float(w0) : 0.f;
                            float4 v0 = __ldg(((const float4*)(src + c0 * IN)) + fl);
                            a0.x += n0 * v0.x; a0.y += n0 * v0.y;
                            a0.z += n0 * v0.z; a0.w += n0 * v0.w;
                        }
                    }
                    float4 s = make_float4(a0.x + a1.x, a0.y + a1.y,
                                           a0.z + a1.z, a0.w + a1.w);
                    s.x += __shfl_xor_sync(0xffffffffu, s.x, 16);
                    s.y += __shfl_xor_sync(0xffffffffu, s.y, 16);
                    s.z += __shfl_xor_sync(0xffffffffu, s.z, 16);
                    s.w += __shfl_xor_sync(0xffffffffu, s.w, 16);
                    if (lane < 16) {
                        float4 t = s;
                        if (k >= 2) {
                            float4 q = __ldg(((const float4*)(prv + nd * IN)) + fl);
                            t.x = 2.f * s.x - q.x; t.y = 2.f * s.y - q.y;
                            t.z = 2.f * s.z - q.z; t.w = 2.f * s.w - q.w;
                        }
                        ((float4*)(dst + nd * IN))[fl] = t;
                        ((float4*)tsw)[fl] = t;
                    }
                } else {
                    // odd width (IN=60): lane-per-feature scalar path
                    int beg = g_rowptr[nd], end = g_rowptr[nd + 1];
                    int f0 = lane, f1 = lane + 32;
                    float s0 = 0.f, s1 = 0.f;
                    for (int e = beg; e < end; e++) {
                        int2 cw = __ldg(&g_colw[e]);
                        float nv = __int_as_float(cw.y);
                        const float* rp = src + cw.x * IN;
                        s0 += nv * __ldg(&rp[f0]);
                        if (f1 < IN) s1 += nv * __ldg(&rp[f1]);
                    }
                    {
                        float t0 = (k >= 2) ? 2.f * s0 - prv[nd * IN + f0] : s0;
                        dst[nd * IN + f0] = t0;
                        tsw[f0] = t0;
                    }
                    if (f1 < IN) {
                        float t1 = (k >= 2) ? 2.f * s1 - prv[nd * IN + f1] : s1;
                        dst[nd * IN + f1] = t1;
                        tsw[f1] = t1;
                    }
                }
            }
            __syncthreads();

            // block GEMM: acc[node, j] (+)= sum_i Ts[node][i] * Ws[i][j]
            constexpr int JS     = (OUT > 32) ? 64 : 32;
            constexpr int GROUPS = TPB / JS;
            constexpr int NPG    = NPB / GROUPS;
            int j = tid % JS;
            int g = tid / JS;
            if (j < OUT) {
                float a[NPG];
#pragma unroll
                for (int q = 0; q < NPG; q++) a[q] = 0.f;
#pragma unroll 4
                for (int i = 0; i < IN; i++) {
                    float wv = Ws[i * OUT + j];
#pragma unroll
                    for (int q = 0; q < NPG; q++)
                        a[q] += wv * Ts[(g * NPG + q) * ST + i];
                }
#pragma unroll
                for (int q = 0; q < NPG; q++) {
                    int node = base + g * NPG + q;
                    if (node < n) {
                        if (k == 0)
                            acc[node * OUT + j] = a[q] + __ldg(&bias[j]);
                        else
                            acc[node * OUT + j] += a[q];
                    }
                }
            }
            __syncthreads();
        }

        if (k >= 1) { prv = src; src = dst; }
        gbar(G);   // T_k fully written & acc updated before step k+1 gathers
    }
}

// ---------------- the single fused kernel -------------------------------------
__global__ __launch_bounds__(TPB, BPS)
void fused_all(const float* __restrict__ x, const void* __restrict__ ei,
               const float* __restrict__ ew,
               const float* __restrict__ W1, const float* __restrict__ b1,
               const float* __restrict__ W2, const float* __restrict__ b2,
               const float* __restrict__ W3, const float* __restrict__ b3,
               const float* __restrict__ W4,
               float* __restrict__ out, int n, int E, int G) {
    __shared__ __align__(16) float Ts[NPB * 65];
    __shared__ float Ws[64 * 60];
    __shared__ int ssum[TPB];

    int tid = threadIdx.x;
    int bid = blockIdx.x;
    int gsz = G * TPB;
    int gid = bid * TPB + tid;

    // phase 0: zero counters + detect int64-vs-int32 edge_index layout
    for (int i = gid; i < n; i += gsz) { g_deg[i] = 0.f; g_cnt[i] = 0; }
    if (bid == 0) {
        __shared__ int bad;
        if (tid == 0) bad = 0;
        __syncthreads();
        int nsamp = E / 2;
        if (nsamp > 4096) nsamp = 4096;
        const int* p32 = (const int*)ei;
        for (int i = tid; i < nsamp; i += TPB)
            if (p32[2 * i + 1] != 0) bad = 1;
        __syncthreads();
        if (tid == 0) g_is64 = (bad == 0) ? 1 : 0;
    }
    gbar(G);

    // phase 1: decode edges (clamped) + degree & in-count
    {
        int is64 = g_is64;
        for (int e = gid; e < E; e += gsz) {
            int s, d;
            if (is64) {
                const long long* p = (const long long*)ei;
                s = (int)p[e];
                d = (int)p[(long long)E + e];
            } else {
                const int* p = (const int*)ei;
                s = p[e];
                d = p[E + e];
            }
            s = (s < 0) ? 0 : ((s >= n) ? n - 1 : s);
            d = (d < 0) ? 0 : ((d >= n) ? n - 1 : d);
            g_srcd[e] = s;
            g_dstd[e] = d;
            atomicAdd(&g_deg[s], ew[e]);
            atomicAdd(&g_cnt[d], 1);
        }
    }
    gbar(G);

    // phase 2: dis + exclusive scan (block 0 only)
    if (bid == 0) {
        for (int i = tid; i < n; i += TPB) {
            float d = g_deg[i];
            g_dis[i] = (d > 0.f) ? (1.f / sqrtf(d)) : 0.f;
        }
        __syncthreads();
        int chunk = (n + TPB - 1) / TPB;
        int beg = tid * chunk; if (beg > n) beg = n;
        int end = beg + chunk; if (end > n) end = n;
        int s = 0;
        for (int i = beg; i < end; i++) s += g_cnt[i];
        ssum[tid] = s;
        __syncthreads();
        for (int off = 1; off < TPB; off <<= 1) {
            int v = (tid >= off) ? ssum[tid - off] : 0;
            __syncthreads();
            ssum[tid] += v;
            __syncthreads();
        }
        int run = (tid == 0) ? 0 : ssum[tid - 1];
        for (int i = beg; i < end; i++) {
            int c = g_cnt[i];
            g_rowptr[i] = run;
            g_cnt[i] = run;   // cursor for scatter
            run += c;
        }
        if (tid == TPB - 1) g_rowptr[n] = ssum[TPB - 1];
    }
    gbar(G);

    // phase 3: scatter packed (col, norm) into CSR order
    for (int e = gid; e < E; e += gsz) {
        int s = g_srcd[e], d = g_dstd[e];
        float nv = -g_dis[s] * ew[e] * g_dis[d];
        int p = atomicAdd(&g_cnt[d], 1);
        g_colw[p] = make_int2(s, __float_as_int(nv));
    }
    gbar(G);

    // layer 1: ChebConv(4 -> 64, K=120) + SiLU
    layer_run<4, 64>(x, g_acc, W1, b1, 120, n, G, Ts, Ws);
    for (int i = gid; i < n * 64; i += gsz) {
        float v = g_acc[i];
        g_h[i] = v / (1.f + expf(-v));
    }
    gbar(G);

    // layer 2: ChebConv(64 -> 60, K=120) + SiLU
    layer_run<64, 60>(g_h, g_acc, W2, b2, 120, n, G, Ts, Ws);
    for (int i = gid; i < n * 60; i += gsz) {
        float v = g_acc[i];
        g_h[i] = v / (1.f + expf(-v));
    }
    gbar(G);

    // layer 3: ChebConv(60 -> 30, K=20) + SiLU
    layer_run<60, 30>(g_h, g_acc, W3, b3, 20, n, G, Ts, Ws);
    for (int i = gid; i < n * 30; i += gsz) {
        float v = g_acc[i];
        g_h[i] = v / (1.f + expf(-v));
    }
    gbar(G);

    // layer 4: ChebConv(30 -> 1, K=1) + sigmoid
    for (int i = gid; i < n; i += gsz) {
        float s = 0.f;
        const float* hp = g_h + i * 30;
#pragma unroll
        for (int k = 0; k < 30; k++) s += hp[k] * __ldg(&W4[k]);
        out[i] = 1.f / (1.f + expf(-s));
    }
}

// ---------------- host orchestration ------------------------------------------
extern "C" void kernel_launch(void* const* d_in, const int* in_sizes, int n_in,
                              void* d_out, int out_size) {
    const float* x  = (const float*)d_in[0];
    const void*  ei = d_in[1];
    const float* ew = (const float*)d_in[2];
    const float* W1 = (const float*)d_in[3];
    const float* b1 = (const float*)d_in[4];
    const float* W2 = (const float*)d_in[5];
    const float* b2 = (const float*)d_in[6];
    const float* W3 = (const float*)d_in[7];
    const float* b3 = (const float*)d_in[8];
    const float* W4 = (const float*)d_in[9];
    float* out = (float*)d_out;

    int n = in_sizes[0] / 4;   // 10000
    int E = in_sizes[2];       // 320000

    static int G = 0;
    if (G == 0) {
        int dev = 0;
        cudaGetDevice(&dev);
        int sms = 0;
        cudaDeviceGetAttribute(&sms, cudaDevAttrMultiProcessorCount, dev);
        int bps = 0;
        cudaOccupancyMaxActiveBlocksPerMultiprocessor(&bps, fused_all, TPB, 0);
        if (sms <= 0) sms = 148;
        if (bps <= 0) bps = 1;
        if (bps > BPS) bps = BPS;
        G = sms * bps;
    }

    fused_all<<<G, TPB>>>(x, ei, ew, W1, b1, W2, b2, W3, b3, W4, out, n, E, G);
}